// round 10
// baseline (speedup 1.0000x reference)
#include <cuda_runtime.h>
#include <cuda_bf16.h>
#include <cstdint>

#define HC 4
#define CDIM 256
#define KDIM 1024
#define MDIM 24
#define TMAX_IT 20
#define RMS_EPS 1e-6f
#define SINK_EPS 1e-6f
#define POST_MULT 2.0f
#define TOK 64
#define THREADS 256

// ---- smem byte offsets ----
#define OFF_CS 0                       // 64 tok x 20 floats = 5120
#define OFF_AH 5376                    // A hi bf16 [64 rows x 264 bf16] = 33792
#define OFF_AL (5376 + 33792)          // A lo
#define A_STR  528                     // bytes per A row (264 bf16)
#define XSB(b)  (OFF_AH + (b)*12992)   // phase-A xs[32][68] floats (aliases A region)
#define PHIB(b) (OFF_AH + (b)*12992 + 8704)
#define SMEM_TOTAL 72960

typedef unsigned long long u64;

// W packed fragment-major, 16B per (gk, ns, lane): [bh 8B | bl 8B]
// offset = ((gk*32 + ns)*32 + lane)*16, gk = k>>4 (0..15), ns = n>>3 (0..31)
__device__ __align__(16) uint4 g_wpk[16 * 32 * 32];

// ---- helpers ----
__device__ __forceinline__ u64 pk2(float lo, float hi) {
    u64 r; asm("mov.b64 %0, {%1, %2};" : "=l"(r) : "f"(lo), "f"(hi)); return r;
}
__device__ __forceinline__ void upk2(u64 v, float& lo, float& hi) {
    asm("mov.b64 {%0, %1}, %2;" : "=f"(lo), "=f"(hi) : "l"(v));
}
__device__ __forceinline__ u64 fma2(u64 a, u64 b, u64 c) {
    u64 d; asm("fma.rn.f32x2 %0, %1, %2, %3;" : "=l"(d) : "l"(a), "l"(b), "l"(c)); return d;
}
__device__ __forceinline__ u64 mul2(u64 a, u64 b) {
    u64 d; asm("mul.rn.f32x2 %0, %1, %2;" : "=l"(d) : "l"(a), "l"(b)); return d;
}
__device__ __forceinline__ float sigmoidf_fast(float v) {
    return __fdividef(1.0f, 1.0f + __expf(-v));
}
__device__ __forceinline__ void split4(float4 v, uint2& h, uint2& l) {
    __nv_bfloat16 ax = __float2bfloat16(v.x), ay = __float2bfloat16(v.y),
                  az = __float2bfloat16(v.z), aw = __float2bfloat16(v.w);
    __nv_bfloat16 bx = __float2bfloat16(v.x - __bfloat162float(ax)),
                  by = __float2bfloat16(v.y - __bfloat162float(ay)),
                  bz = __float2bfloat16(v.z - __bfloat162float(az)),
                  bw = __float2bfloat16(v.w - __bfloat162float(aw));
    h.x = ((uint32_t)__bfloat16_as_ushort(ay) << 16) | __bfloat16_as_ushort(ax);
    h.y = ((uint32_t)__bfloat16_as_ushort(aw) << 16) | __bfloat16_as_ushort(az);
    l.x = ((uint32_t)__bfloat16_as_ushort(by) << 16) | __bfloat16_as_ushort(bx);
    l.y = ((uint32_t)__bfloat16_as_ushort(bw) << 16) | __bfloat16_as_ushort(bz);
}
__device__ __forceinline__ void mma_bf16(float4& d, uint4 a, uint2 b) {
    asm volatile("mma.sync.aligned.m16n8k16.row.col.f32.bf16.bf16.f32 "
        "{%0,%1,%2,%3}, {%4,%5,%6,%7}, {%8,%9}, {%0,%1,%2,%3};"
        : "+f"(d.x), "+f"(d.y), "+f"(d.z), "+f"(d.w)
        : "r"(a.x), "r"(a.y), "r"(a.z), "r"(a.w), "r"(b.x), "r"(b.y));
}

// =====================================================================
// W pack: one 16B record per (gk, ns, lane) holding hi|lo fragments
__global__ void w_pack(const float* __restrict__ W) {
    int i = blockIdx.x * 256 + threadIdx.x;          // 65536 elements
    int n = i >> 8, k = i & 255;
    float v = W[n * 256 + k];
    __nv_bfloat16 h = __float2bfloat16(v);
    __nv_bfloat16 l = __float2bfloat16(v - __bfloat162float(h));
    int gk = k >> 4, k_in = k & 15, ns = n >> 3;
    int lane = ((n & 7) << 2) | ((k_in >> 1) & 3);
    char* base = (char*)&g_wpk[(gk * 32 + ns) * 32 + lane];
    int sub = ((k_in >> 3) << 2) + ((k_in & 1) << 1);
    *(__nv_bfloat16*)(base + sub)     = h;
    *(__nv_bfloat16*)(base + 8 + sub) = l;
}

// =====================================================================
__global__ __launch_bounds__(THREADS, 3)
void mhc_mma(const float* __restrict__ x, const float* __restrict__ phi,
             const float* __restrict__ bvec, const float* __restrict__ apre_p,
             const float* __restrict__ apost_p, const float* __restrict__ ares_p,
             float* __restrict__ out)
{
    extern __shared__ char smem[];
    float* s_cs = (float*)(smem + OFF_CS);
    const int tid = threadIdx.x, lane = tid & 31, wid = tid >> 5;
    const int tok0 = blockIdx.x * TOK;
    const int t0 = wid * 8;

    const float apre = *apre_p, apost = *apost_p, ares = *ares_p;

    // zero phi pads (m 24..31) in both buffers
    for (int l = tid; l < 512; l += THREADS) {
        int b = l >> 8, ll = l & 255;
        ((float*)(smem + PHIB(b)))[(ll >> 3) * 32 + 24 + (ll & 7)] = 0.0f;
    }

    // ---------- Phase A: logits = x . phi (double-buffered, 32-k chunks) ----------
    u64 acc2[4] = {0ull, 0ull, 0ull, 0ull};
    {
        for (int r = 0; r < 2; r++) {
            int slot = r * THREADS + tid, tk = slot >> 3, kq = slot & 7;
            float4 v = *(const float4*)(x + (size_t)(tok0 + tk) * KDIM + kq * 4);
            float* xs = (float*)(smem + XSB(0));
            xs[(kq*4+0)*68 + tk] = v.x; xs[(kq*4+1)*68 + tk] = v.y;
            xs[(kq*4+2)*68 + tk] = v.z; xs[(kq*4+3)*68 + tk] = v.w;
        }
        for (int l = tid; l < 32 * MDIM; l += THREADS)
            ((float*)(smem + PHIB(0)))[(l / MDIM) * 32 + (l % MDIM)] = phi[l];
    }
    __syncthreads();
    for (int kc = 0; kc < 32; kc++) {
        if (kc < 31) {
            int nb = (kc + 1) & 1, kb = (kc + 1) * 32;
            float* xs = (float*)(smem + XSB(nb));
            for (int r = 0; r < 2; r++) {
                int slot = r * THREADS + tid, tk = slot >> 3, kq = slot & 7;
                float4 v = *(const float4*)(x + (size_t)(tok0 + tk) * KDIM + kb + kq * 4);
                xs[(kq*4+0)*68 + tk] = v.x; xs[(kq*4+1)*68 + tk] = v.y;
                xs[(kq*4+2)*68 + tk] = v.z; xs[(kq*4+3)*68 + tk] = v.w;
            }
            float* ph = (float*)(smem + PHIB(nb));
            for (int l = tid; l < 32 * MDIM; l += THREADS)
                ph[(l / MDIM) * 32 + (l % MDIM)] = phi[kb * MDIM + l];
        }
        const float* xs = (const float*)(smem + XSB(kc & 1));
        const float* ph = (const float*)(smem + PHIB(kc & 1));
        #pragma unroll 8
        for (int k = 0; k < 32; k++) {
            float pm = ph[k * 32 + lane];
            u64 pm2 = pk2(pm, pm);
            ulonglong2 xa = *(const ulonglong2*)(&xs[k * 68 + t0]);
            ulonglong2 xb = *(const ulonglong2*)(&xs[k * 68 + t0 + 4]);
            acc2[0] = fma2(xa.x, pm2, acc2[0]);
            acc2[1] = fma2(xa.y, pm2, acc2[1]);
            acc2[2] = fma2(xb.x, pm2, acc2[2]);
            acc2[3] = fma2(xb.y, pm2, acc2[3]);
        }
        __syncthreads();
    }

    float l8[8];
    #pragma unroll
    for (int j = 0; j < 4; j++) upk2(acc2[j], l8[2*j], l8[2*j+1]);
    const float bm = (lane < MDIM) ? bvec[lane] : 0.0f;
    float yv[8];
    #pragma unroll
    for (int t = 0; t < 8; t++) {
        float s = (lane < MDIM) ? l8[t] * l8[t] : 0.0f;
        s += __shfl_xor_sync(~0u, s, 16); s += __shfl_xor_sync(~0u, s, 8);
        s += __shfl_xor_sync(~0u, s, 4);  s += __shfl_xor_sync(~0u, s, 2);
        s += __shfl_xor_sync(~0u, s, 1);
        yv[t] = l8[t] * rsqrtf(s * (1.0f / 24.0f) + RMS_EPS) + bm;
    }

    // ---------- Phase B: Sinkhorn ----------
    float P[4];
    #pragma unroll
    for (int tp = 0; tp < 4; tp++) {
        int src = 8 + (lane & 15);
        float ra = __shfl_sync(~0u, yv[2*tp], src);
        float rb = __shfl_sync(~0u, yv[2*tp+1], src);
        P[tp] = __expf(ares * ((lane < 16) ? ra : rb));
    }
    #pragma unroll
    for (int it = 0; it < TMAX_IT; it++) {
        #pragma unroll
        for (int tp = 0; tp < 4; tp++) {
            float s1 = P[tp] + __shfl_xor_sync(~0u, P[tp], 1);
            s1 += __shfl_xor_sync(~0u, s1, 2);
            P[tp] = __fdividef(P[tp], s1 + SINK_EPS);
        }
        #pragma unroll
        for (int tp = 0; tp < 4; tp++) {
            float s1 = P[tp] + __shfl_xor_sync(~0u, P[tp], 4);
            s1 += __shfl_xor_sync(~0u, s1, 8);
            P[tp] = __fdividef(P[tp], s1 + SINK_EPS);
        }
    }
    #pragma unroll
    for (int tp = 0; tp < 4; tp++) {
        int tl = t0 + 2*tp;
        if (lane < 16) s_cs[tl * 20 + lane] = P[tp];
        else           s_cs[(tl + 1) * 20 + (lane - 16)] = P[tp];
    }

    // ---------- Phase C: h_post + xin -> A tiles (bf16 hi/lo, row-major pad 264) ----------
    #pragma unroll
    for (int t = 0; t < 8; t++) {
        int tl = t0 + t, tok = tok0 + tl;
        float yp = __shfl_sync(~0u, yv[t], 4 + (lane & 3));
        if (lane < 4) s_cs[tl * 20 + 16 + lane] = POST_MULT * sigmoidf_fast(apost * yp);
        float hp0 = sigmoidf_fast(apre * __shfl_sync(~0u, yv[t], 0));
        float hp1 = sigmoidf_fast(apre * __shfl_sync(~0u, yv[t], 1));
        float hp2 = sigmoidf_fast(apre * __shfl_sync(~0u, yv[t], 2));
        float hp3 = sigmoidf_fast(apre * __shfl_sync(~0u, yv[t], 3));
        const float4* xt = (const float4*)(x + (size_t)tok * KDIM);
        float4 sA = make_float4(0,0,0,0), sB = make_float4(0,0,0,0);
        #pragma unroll
        for (int i = 0; i < HC; i++) {
            float hp = (i==0)?hp0:(i==1)?hp1:(i==2)?hp2:hp3;
            float4 a = xt[i * 64 + lane], b = xt[i * 64 + 32 + lane];
            sA.x = fmaf(hp,a.x,sA.x); sA.y = fmaf(hp,a.y,sA.y);
            sA.z = fmaf(hp,a.z,sA.z); sA.w = fmaf(hp,a.w,sA.w);
            sB.x = fmaf(hp,b.x,sB.x); sB.y = fmaf(hp,b.y,sB.y);
            sB.z = fmaf(hp,b.z,sB.z); sB.w = fmaf(hp,b.w,sB.w);
        }
        uint2 hA, lA, hB, lB;
        split4(sA, hA, lA); split4(sB, hB, lB);
        *(uint2*)(smem + OFF_AH + tl*A_STR + lane*8)       = hA;
        *(uint2*)(smem + OFF_AL + tl*A_STR + lane*8)       = lA;
        *(uint2*)(smem + OFF_AH + tl*A_STR + 256 + lane*8) = hB;
        *(uint2*)(smem + OFF_AL + tl*A_STR + 256 + lane*8) = lB;
    }
    __syncthreads();

    // ---------- Phase D: F = xin @ W^T (mma.sync, B direct from L2) + fused epilogue ----------
    const int mt = wid & 3;        // m-tile (16 rows)
    const int nh = wid >> 2;       // n half (16 of 32 n-subtiles)
    const int r0 = mt * 16 + (lane >> 2);        // local token row (and r0+8)
    const char* pah = smem + OFF_AH + r0*A_STR + (lane&3)*4;
    const char* pal = smem + OFF_AL + r0*A_STR + (lane&3)*4;
    const int c0 = (lane & 3) * 2;

    #pragma unroll
    for (int jb = 0; jb < 4; jb++) {
        const int nsb = nh * 16 + jb * 4;
        float4 D0 = make_float4(0,0,0,0), D1 = D0, D2 = D0, D3 = D0;
        const uint4* pb = g_wpk + nsb * 32 + lane;
        #pragma unroll
        for (int gk = 0; gk < 16; gk++) {
            int gko = gk * 32;
            uint4 Ah, Al;
            Ah.x = *(const uint32_t*)(pah + gko);
            Ah.y = *(const uint32_t*)(pah + 8*A_STR + gko);
            Ah.z = *(const uint32_t*)(pah + gko + 16);
            Ah.w = *(const uint32_t*)(pah + 8*A_STR + gko + 16);
            Al.x = *(const uint32_t*)(pal + gko);
            Al.y = *(const uint32_t*)(pal + 8*A_STR + gko);
            Al.z = *(const uint32_t*)(pal + gko + 16);
            Al.w = *(const uint32_t*)(pal + 8*A_STR + gko + 16);
            uint4 B0 = pb[gk*1024 + 0*32];
            uint4 B1 = pb[gk*1024 + 1*32];
            uint4 B2 = pb[gk*1024 + 2*32];
            uint4 B3 = pb[gk*1024 + 3*32];
            mma_bf16(D0, Ah, make_uint2(B0.x, B0.y));
            mma_bf16(D0, Al, make_uint2(B0.x, B0.y));
            mma_bf16(D0, Ah, make_uint2(B0.z, B0.w));
            mma_bf16(D1, Ah, make_uint2(B1.x, B1.y));
            mma_bf16(D1, Al, make_uint2(B1.x, B1.y));
            mma_bf16(D1, Ah, make_uint2(B1.z, B1.w));
            mma_bf16(D2, Ah, make_uint2(B2.x, B2.y));
            mma_bf16(D2, Al, make_uint2(B2.x, B2.y));
            mma_bf16(D2, Ah, make_uint2(B2.z, B2.w));
            mma_bf16(D3, Ah, make_uint2(B3.x, B3.y));
            mma_bf16(D3, Al, make_uint2(B3.x, B3.y));
            mma_bf16(D3, Ah, make_uint2(B3.z, B3.w));
        }
        // fused epilogue for these 4 n-subtiles
        const size_t tokA = tok0 + r0, tokB = tokA + 8;
        #pragma unroll
        for (int jj = 0; jj < 4; jj++) {
            float4 Dv = (jj==0) ? D0 : (jj==1) ? D1 : (jj==2) ? D2 : D3;
            int c = (nsb + jj) * 8 + c0;
            u64 xa[HC], xbv[HC];
            #pragma unroll
            for (int ii = 0; ii < HC; ii++) {
                xa[ii]  = *(const u64*)(x + tokA * KDIM + ii * 256 + c);
                xbv[ii] = *(const u64*)(x + tokB * KDIM + ii * 256 + c);
            }
            u64 fA = pk2(Dv.x, Dv.y), fB = pk2(Dv.z, Dv.w);
            #pragma unroll
            for (int o = 0; o < HC; o++) {
                float hpA = s_cs[r0 * 20 + 16 + o];
                float hpB = s_cs[(r0 + 8) * 20 + 16 + o];
                u64 accA = mul2(pk2(hpA, hpA), fA);
                u64 accB = mul2(pk2(hpB, hpB), fB);
                #pragma unroll
                for (int ii = 0; ii < HC; ii++) {
                    float pA = s_cs[r0 * 20 + o * 4 + ii];
                    float pB = s_cs[(r0 + 8) * 20 + o * 4 + ii];
                    accA = fma2(pk2(pA, pA), xa[ii], accA);
                    accB = fma2(pk2(pB, pB), xbv[ii], accB);
                }
                *(u64*)(out + tokA * KDIM + o * 256 + c) = accA;
                *(u64*)(out + tokB * KDIM + o * 256 + c) = accB;
            }
        }
    }
}

// =====================================================================
extern "C" void kernel_launch(void* const* d_in, const int* in_sizes, int n_in,
                              void* d_out, int out_size)
{
    const float* x     = (const float*)d_in[0];
    const float* phi   = (const float*)d_in[1];
    const float* bvec  = (const float*)d_in[2];
    const float* apre  = (const float*)d_in[3];
    const float* apost = (const float*)d_in[4];
    const float* ares  = (const float*)d_in[5];
    const float* W     = (const float*)d_in[6];
    float* out = (float*)d_out;

    int tokens = in_sizes[0] / KDIM;

    static bool attr_set = false;
    if (!attr_set) {
        cudaFuncSetAttribute(mhc_mma, cudaFuncAttributeMaxDynamicSharedMemorySize, SMEM_TOTAL);
        attr_set = true;
    }
    w_pack<<<256, 256>>>(W);
    mhc_mma<<<tokens / TOK, THREADS, SMEM_TOTAL>>>(x, phi, bvec, apre, apost, ares, out);
}

// round 11
// speedup vs baseline: 2.8172x; 2.8172x over previous
#include <cuda_runtime.h>
#include <cuda_bf16.h>
#include <cstdint>

#define HC 4
#define CDIM 256
#define KDIM 1024
#define MDIM 24
#define TMAX_IT 20
#define RMS_EPS 1e-6f
#define SINK_EPS 1e-6f
#define POST_MULT 2.0f
#define TOK 128
#define THREADS 512

// ---- smem byte offsets (R6 layout) ----
#define OFF_CS 256                     // 128 tok x 20 floats
#define OFF_AH 16384                   // A hi bf16 [128 x 264] = 67584
#define OFF_AL 83968                   // A lo
#define OFF_B  151552                  // 64 KB region: phase-D W chunks; phase-A lgp aliases
#define OFF_D  16384                   // f fp32 [128][264] = 135168 (aliases A tiles)
#define D_STR  264
#define A_STR  528
// phase-A aliases:
#define XA(b)  (OFF_AH + (b)*18432)    // x-chunk hi bf16 [128 x 72] stride 144 B
#define XL(b)  (OFF_AL + (b)*18432)    // x-chunk lo
#define X_STR  144
#define OFF_LG OFF_B                   // float lgp[2][128][28] = 28672
#define SMEM_TOTAL 217088

typedef unsigned long long u64;

// W packed fragment-major (R6-validated): [kchunk 0..3][hi(32KB)|lo(32KB)]
__device__ __align__(16) char g_wpk[4 * 65536];
// phi packed: one uint4 per (gk 0..63, ns 0..2, lane): [bh 8B | bl 8B]
__device__ __align__(16) uint4 g_ppk[64 * 3 * 32];

// ---- helpers ----
__device__ __forceinline__ u64 pk2(float lo, float hi) {
    u64 r; asm("mov.b64 %0, {%1, %2};" : "=l"(r) : "f"(lo), "f"(hi)); return r;
}
__device__ __forceinline__ void upk2(u64 v, float& lo, float& hi) {
    asm("mov.b64 {%0, %1}, %2;" : "=f"(lo), "=f"(hi) : "l"(v));
}
__device__ __forceinline__ u64 fma2(u64 a, u64 b, u64 c) {
    u64 d; asm("fma.rn.f32x2 %0, %1, %2, %3;" : "=l"(d) : "l"(a), "l"(b), "l"(c)); return d;
}
__device__ __forceinline__ float sigmoidf_fast(float v) {
    return __fdividef(1.0f, 1.0f + __expf(-v));
}
__device__ __forceinline__ void split4(float4 v, uint2& h, uint2& l) {
    __nv_bfloat16 ax = __float2bfloat16(v.x), ay = __float2bfloat16(v.y),
                  az = __float2bfloat16(v.z), aw = __float2bfloat16(v.w);
    __nv_bfloat16 bx = __float2bfloat16(v.x - __bfloat162float(ax)),
                  by = __float2bfloat16(v.y - __bfloat162float(ay)),
                  bz = __float2bfloat16(v.z - __bfloat162float(az)),
                  bw = __float2bfloat16(v.w - __bfloat162float(aw));
    h.x = ((uint32_t)__bfloat16_as_ushort(ay) << 16) | __bfloat16_as_ushort(ax);
    h.y = ((uint32_t)__bfloat16_as_ushort(aw) << 16) | __bfloat16_as_ushort(az);
    l.x = ((uint32_t)__bfloat16_as_ushort(by) << 16) | __bfloat16_as_ushort(bx);
    l.y = ((uint32_t)__bfloat16_as_ushort(bw) << 16) | __bfloat16_as_ushort(bz);
}
__device__ __forceinline__ void mma_bf16(float4& d, uint4 a, uint2 b) {
    asm volatile("mma.sync.aligned.m16n8k16.row.col.f32.bf16.bf16.f32 "
        "{%0,%1,%2,%3}, {%4,%5,%6,%7}, {%8,%9}, {%0,%1,%2,%3};"
        : "+f"(d.x), "+f"(d.y), "+f"(d.z), "+f"(d.w)
        : "r"(a.x), "r"(a.y), "r"(a.z), "r"(a.w), "r"(b.x), "r"(b.y));
}
// pack 2 floats -> bf16x2 (v0 in low half), round-nearest
__device__ __forceinline__ uint32_t cvt2(float v0, float v1) {
    uint32_t r; asm("cvt.rn.bf16x2.f32 %0, %1, %2;" : "=r"(r) : "f"(v1), "f"(v0)); return r;
}

// =====================================================================
// W pack (R6-validated layout): [kc][hi|lo], record 8B per (ks, ns, lane)
__global__ void w_pack(const float* __restrict__ W) {
    int i = blockIdx.x * 256 + threadIdx.x;
    int n = i >> 8, k = i & 255;
    float v = W[n * 256 + k];
    __nv_bfloat16 h = __float2bfloat16(v);
    __nv_bfloat16 l = __float2bfloat16(v - __bfloat162float(h));
    int kc = k >> 6, ks = (k & 63) >> 4, k_in = k & 15, ns = n >> 3;
    int lane = ((n & 7) << 2) | ((k_in >> 1) & 3);
    int off = (((ks * 32 + ns) * 32 + lane) << 3) + ((k_in >> 3) << 2) + ((k_in & 1) << 1);
    *(__nv_bfloat16*)(g_wpk + kc * 65536 + off)         = h;
    *(__nv_bfloat16*)(g_wpk + kc * 65536 + 32768 + off) = l;
}

// phi pack: B-fragment records, n = m (24), K = 1024
__global__ void phi_pack(const float* __restrict__ phi) {
    int i = blockIdx.x * 256 + threadIdx.x;      // 24576
    int m = i >> 10, k = i & 1023;
    float v = phi[k * 24 + m];
    __nv_bfloat16 h = __float2bfloat16(v);
    __nv_bfloat16 l = __float2bfloat16(v - __bfloat162float(h));
    int gk = k >> 4, k_in = k & 15, ns = m >> 3;
    int lane = ((m & 7) << 2) | ((k_in >> 1) & 3);
    char* base = (char*)&g_ppk[(gk * 3 + ns) * 32 + lane];
    int sub = ((k_in >> 3) << 2) + ((k_in & 1) << 1);
    *(__nv_bfloat16*)(base + sub)     = h;
    *(__nv_bfloat16*)(base + 8 + sub) = l;
}

// =====================================================================
__global__ __launch_bounds__(THREADS, 1)
void mhc_mma(const float* __restrict__ x, const float* __restrict__ bvec,
             const float* __restrict__ apre_p, const float* __restrict__ apost_p,
             const float* __restrict__ ares_p, float* __restrict__ out)
{
    extern __shared__ char smem[];
    float* s_cs = (float*)(smem + OFF_CS);
    const int tid = threadIdx.x, lane = tid & 31, wid = tid >> 5;
    const int tok0 = blockIdx.x * TOK;
    const int t0 = wid * 8;

    const float apre = *apre_p, apost = *apost_p, ares = *ares_p;

    // ---------- Phase A: logits = x . phi via mma.sync (bf16 trunc-split) ----------
    const int amt = wid & 7;       // m-tile
    const int akh = wid >> 3;      // k half
    float4 DL0 = make_float4(0,0,0,0), DL1 = DL0, DL2 = DL0;

    // chunk conversion: 64 k per chunk; thread -> tok=tid>>2, kq=(tid&3)*16
    #define CONV_CHUNK(KC, BUF) do {                                              \
        int tok_ = tid >> 2, kq_ = (tid & 3) * 16;                                \
        const float4* src_ = (const float4*)(x + (size_t)(tok0 + tok_) * KDIM     \
                                             + (KC) * 64 + kq_);                  \
        char* dh_ = smem + XA(BUF) + tok_ * X_STR + kq_ * 2;                      \
        char* dl_ = smem + XL(BUF) + tok_ * X_STR + kq_ * 2;                      \
        _Pragma("unroll")                                                         \
        for (int j_ = 0; j_ < 4; j_++) {                                          \
            float4 v_ = src_[j_];                                                 \
            uint32_t ux_ = __float_as_uint(v_.x), uy_ = __float_as_uint(v_.y);    \
            uint32_t uz_ = __float_as_uint(v_.z), uw_ = __float_as_uint(v_.w);    \
            uint32_t h01_ = __byte_perm(ux_, uy_, 0x7632);                        \
            uint32_t h23_ = __byte_perm(uz_, uw_, 0x7632);                        \
            float l0_ = v_.x - __uint_as_float(ux_ & 0xFFFF0000u);                \
            float l1_ = v_.y - __uint_as_float(uy_ & 0xFFFF0000u);                \
            float l2_ = v_.z - __uint_as_float(uz_ & 0xFFFF0000u);                \
            float l3_ = v_.w - __uint_as_float(uw_ & 0xFFFF0000u);                \
            *(uint2*)(dh_ + j_ * 8) = make_uint2(h01_, h23_);                     \
            *(uint2*)(dl_ + j_ * 8) = make_uint2(cvt2(l0_, l1_), cvt2(l2_, l3_)); \
        }                                                                         \
    } while (0)

    CONV_CHUNK(0, 0);
    __syncthreads();
    for (int kc = 0; kc < 16; kc++) {
        if (kc < 15) CONV_CHUNK(kc + 1, (kc + 1) & 1);
        const char* xah = smem + XA(kc & 1);
        const char* xal = smem + XL(kc & 1);
        const int r = amt * 16 + (lane >> 2);
        #pragma unroll
        for (int gl = 0; gl < 2; gl++) {
            int gkl = akh * 2 + gl;
            const char* pa = xah + r * X_STR + gkl * 32 + (lane & 3) * 4;
            const char* pl = xal + r * X_STR + gkl * 32 + (lane & 3) * 4;
            uint4 Ah, Al;
            Ah.x = *(const uint32_t*)pa;               Ah.y = *(const uint32_t*)(pa + 8 * X_STR);
            Ah.z = *(const uint32_t*)(pa + 16);        Ah.w = *(const uint32_t*)(pa + 8 * X_STR + 16);
            Al.x = *(const uint32_t*)pl;               Al.y = *(const uint32_t*)(pl + 8 * X_STR);
            Al.z = *(const uint32_t*)(pl + 16);        Al.w = *(const uint32_t*)(pl + 8 * X_STR + 16);
            int gk = kc * 4 + gkl;
            const uint4* pb = g_ppk + gk * 96 + lane;
            uint4 B0 = pb[0], B1 = pb[32], B2 = pb[64];
            mma_bf16(DL0, Ah, make_uint2(B0.x, B0.y));
            mma_bf16(DL0, Al, make_uint2(B0.x, B0.y));
            mma_bf16(DL0, Ah, make_uint2(B0.z, B0.w));
            mma_bf16(DL1, Ah, make_uint2(B1.x, B1.y));
            mma_bf16(DL1, Al, make_uint2(B1.x, B1.y));
            mma_bf16(DL1, Ah, make_uint2(B1.z, B1.w));
            mma_bf16(DL2, Ah, make_uint2(B2.x, B2.y));
            mma_bf16(DL2, Al, make_uint2(B2.x, B2.y));
            mma_bf16(DL2, Ah, make_uint2(B2.z, B2.w));
        }
        __syncthreads();
    }

    // write k-half partials to lgp[2][128][28]
    float* lgp = (float*)(smem + OFF_LG);
    {
        int r = amt * 16 + (lane >> 2), cb = (lane & 3) * 2;
        #pragma unroll
        for (int ns = 0; ns < 3; ns++) {
            float4 Dv = (ns == 0) ? DL0 : (ns == 1) ? DL1 : DL2;
            int c = ns * 8 + cb;
            *(float2*)&lgp[(akh * 128 + r) * 28 + c]     = make_float2(Dv.x, Dv.y);
            *(float2*)&lgp[(akh * 128 + r + 8) * 28 + c] = make_float2(Dv.z, Dv.w);
        }
    }
    __syncthreads();

    float l8[8];
    #pragma unroll
    for (int t = 0; t < 8; t++)
        l8[t] = (lane < MDIM)
              ? lgp[(t0 + t) * 28 + lane] + lgp[(128 + t0 + t) * 28 + lane] : 0.0f;

    const float bm = (lane < MDIM) ? bvec[lane] : 0.0f;
    float yv[8];
    #pragma unroll
    for (int t = 0; t < 8; t++) {
        float s = l8[t] * l8[t];
        s += __shfl_xor_sync(~0u, s, 16); s += __shfl_xor_sync(~0u, s, 8);
        s += __shfl_xor_sync(~0u, s, 4);  s += __shfl_xor_sync(~0u, s, 2);
        s += __shfl_xor_sync(~0u, s, 1);
        yv[t] = l8[t] * rsqrtf(s * (1.0f / 24.0f) + RMS_EPS) + bm;
    }

    // ---------- Phase B: Sinkhorn ----------
    float P[4];
    #pragma unroll
    for (int tp = 0; tp < 4; tp++) {
        int src = 8 + (lane & 15);
        float ra = __shfl_sync(~0u, yv[2*tp], src);
        float rb = __shfl_sync(~0u, yv[2*tp+1], src);
        P[tp] = __expf(ares * ((lane < 16) ? ra : rb));
    }
    #pragma unroll
    for (int it = 0; it < TMAX_IT; it++) {
        #pragma unroll
        for (int tp = 0; tp < 4; tp++) {
            float s1 = P[tp] + __shfl_xor_sync(~0u, P[tp], 1);
            s1 += __shfl_xor_sync(~0u, s1, 2);
            P[tp] = __fdividef(P[tp], s1 + SINK_EPS);
        }
        #pragma unroll
        for (int tp = 0; tp < 4; tp++) {
            float s1 = P[tp] + __shfl_xor_sync(~0u, P[tp], 4);
            s1 += __shfl_xor_sync(~0u, s1, 8);
            P[tp] = __fdividef(P[tp], s1 + SINK_EPS);
        }
    }
    #pragma unroll
    for (int tp = 0; tp < 4; tp++) {
        int tl = t0 + 2*tp;
        if (lane < 16) s_cs[tl * 20 + lane] = P[tp];
        else           s_cs[(tl + 1) * 20 + (lane - 16)] = P[tp];
    }

    // ---------- Phase C: h_post + xin -> A tiles (bf16 hi/lo, pad 264) ----------
    #pragma unroll
    for (int t = 0; t < 8; t++) {
        int tl = t0 + t, tok = tok0 + tl;
        float yp = __shfl_sync(~0u, yv[t], 4 + (lane & 3));
        if (lane < 4) s_cs[tl * 20 + 16 + lane] = POST_MULT * sigmoidf_fast(apost * yp);
        float hp0 = sigmoidf_fast(apre * __shfl_sync(~0u, yv[t], 0));
        float hp1 = sigmoidf_fast(apre * __shfl_sync(~0u, yv[t], 1));
        float hp2 = sigmoidf_fast(apre * __shfl_sync(~0u, yv[t], 2));
        float hp3 = sigmoidf_fast(apre * __shfl_sync(~0u, yv[t], 3));
        const float4* xt = (const float4*)(x + (size_t)tok * KDIM);
        float4 sA = make_float4(0,0,0,0), sB = make_float4(0,0,0,0);
        #pragma unroll
        for (int i = 0; i < HC; i++) {
            float hp = (i==0)?hp0:(i==1)?hp1:(i==2)?hp2:hp3;
            float4 a = xt[i * 64 + lane], b = xt[i * 64 + 32 + lane];
            sA.x = fmaf(hp,a.x,sA.x); sA.y = fmaf(hp,a.y,sA.y);
            sA.z = fmaf(hp,a.z,sA.z); sA.w = fmaf(hp,a.w,sA.w);
            sB.x = fmaf(hp,b.x,sB.x); sB.y = fmaf(hp,b.y,sB.y);
            sB.z = fmaf(hp,b.z,sB.z); sB.w = fmaf(hp,b.w,sB.w);
        }
        uint2 hA, lA, hB, lB;
        split4(sA, hA, lA); split4(sB, hB, lB);
        *(uint2*)(smem + OFF_AH + tl*A_STR + lane*8)       = hA;
        *(uint2*)(smem + OFF_AL + tl*A_STR + lane*8)       = lA;
        *(uint2*)(smem + OFF_AH + tl*A_STR + 256 + lane*8) = hB;
        *(uint2*)(smem + OFF_AL + tl*A_STR + 256 + lane*8) = lB;
    }
    __syncthreads();

    // ---------- Phase D: F = xin @ W^T via mma.sync (R6-validated) ----------
    const int mt = wid & 7;
    const int nh = wid >> 3;
    float4 D[16];
    #pragma unroll
    for (int j = 0; j < 16; j++) D[j] = make_float4(0,0,0,0);

    const char* pah = smem + OFF_AH + (mt*16 + (lane>>2))*A_STR + (lane&3)*4;
    const char* pal = smem + OFF_AL + (mt*16 + (lane>>2))*A_STR + (lane&3)*4;

    for (int kc = 0; kc < 4; kc++) {
        {
            const uint4* src = (const uint4*)(g_wpk + kc * 65536);
            uint4* dst = (uint4*)(smem + OFF_B);
            #pragma unroll
            for (int j = 0; j < 8; j++) dst[j * THREADS + tid] = src[j * THREADS + tid];
        }
        __syncthreads();
        #pragma unroll
        for (int ks = 0; ks < 4; ks++) {
            int gko = (kc * 4 + ks) * 32;
            uint4 Ah, Al;
            Ah.x = *(const uint32_t*)(pah + gko);
            Ah.y = *(const uint32_t*)(pah + 8*A_STR + gko);
            Ah.z = *(const uint32_t*)(pah + gko + 16);
            Ah.w = *(const uint32_t*)(pah + 8*A_STR + gko + 16);
            Al.x = *(const uint32_t*)(pal + gko);
            Al.y = *(const uint32_t*)(pal + 8*A_STR + gko);
            Al.z = *(const uint32_t*)(pal + gko + 16);
            Al.w = *(const uint32_t*)(pal + 8*A_STR + gko + 16);
            const char* pb = smem + OFF_B + ((ks*32 + nh*16)*32 + lane)*8;
            #pragma unroll
            for (int j = 0; j < 16; j++) {
                uint2 bh = *(const uint2*)(pb + j*256);
                uint2 bl = *(const uint2*)(pb + 32768 + j*256);
                mma_bf16(D[j], Ah, bh);
                mma_bf16(D[j], Al, bh);
                mma_bf16(D[j], Ah, bl);
            }
        }
        __syncthreads();
    }

    // ---------- stage F into s_D fp32 [128][264] ----------
    float* sD = (float*)(smem + OFF_D);
    {
        int r0 = mt*16 + (lane>>2);
        int cb = nh*128 + (lane&3)*2;
        #pragma unroll
        for (int j = 0; j < 16; j++) {
            int col = cb + j*8;
            *(float2*)&sD[r0*D_STR + col]     = make_float2(D[j].x, D[j].y);
            *(float2*)&sD[(r0+8)*D_STR + col] = make_float2(D[j].z, D[j].w);
        }
    }
    __syncthreads();

    // ---------- epilogue: out = P@x + hpost * f ----------
    const int cx = lane;
    #pragma unroll
    for (int i = 0; i < 8; i++) {
        int tl = t0 + i, tok = tok0 + tl;
        const u64* xb = (const u64*)(x + (size_t)tok * KDIM);
        ulonglong2 xpA[HC], xpB[HC];
        #pragma unroll
        for (int ii = 0; ii < HC; ii++) {
            xpA[ii] = *(const ulonglong2*)(xb + ii * 128 + cx * 2);
            xpB[ii] = *(const ulonglong2*)(xb + ii * 128 + 64 + cx * 2);
        }
        float4 fA = *(const float4*)(sD + tl * D_STR + 4 * cx);
        float4 fB = *(const float4*)(sD + tl * D_STR + 128 + 4 * cx);
        u64* ob = (u64*)(out + (size_t)tok * KDIM);
        #pragma unroll
        for (int o = 0; o < HC; o++) {
            float hp = s_cs[tl * 20 + 16 + o];
            u64 hp2 = pk2(hp, hp);
            u64 r0 = fma2(hp2, pk2(fA.x, fA.y), 0ull);
            u64 r1 = fma2(hp2, pk2(fA.z, fA.w), 0ull);
            u64 r2 = fma2(hp2, pk2(fB.x, fB.y), 0ull);
            u64 r3 = fma2(hp2, pk2(fB.z, fB.w), 0ull);
            #pragma unroll
            for (int ii = 0; ii < HC; ii++) {
                float p = s_cs[tl * 20 + o * 4 + ii];
                u64 p2 = pk2(p, p);
                r0 = fma2(p2, xpA[ii].x, r0); r1 = fma2(p2, xpA[ii].y, r1);
                r2 = fma2(p2, xpB[ii].x, r2); r3 = fma2(p2, xpB[ii].y, r3);
            }
            *(ulonglong2*)(ob + o * 128 + cx * 2)      = make_ulonglong2(r0, r1);
            *(ulonglong2*)(ob + o * 128 + 64 + cx * 2) = make_ulonglong2(r2, r3);
        }
    }
}

// =====================================================================
extern "C" void kernel_launch(void* const* d_in, const int* in_sizes, int n_in,
                              void* d_out, int out_size)
{
    const float* x     = (const float*)d_in[0];
    const float* phi   = (const float*)d_in[1];
    const float* bvec  = (const float*)d_in[2];
    const float* apre  = (const float*)d_in[3];
    const float* apost = (const float*)d_in[4];
    const float* ares  = (const float*)d_in[5];
    const float* W     = (const float*)d_in[6];
    float* out = (float*)d_out;

    int tokens = in_sizes[0] / KDIM;

    static bool attr_set = false;
    if (!attr_set) {
        cudaFuncSetAttribute(mhc_mma, cudaFuncAttributeMaxDynamicSharedMemorySize, SMEM_TOTAL);
        attr_set = true;
    }
    w_pack<<<256, 256>>>(W);
    phi_pack<<<96, 256>>>(phi);
    mhc_mma<<<tokens / TOK, THREADS, SMEM_TOTAL>>>(x, bvec, apre, apost, ares, out);
}

// round 12
// speedup vs baseline: 2.8857x; 1.0243x over previous
#include <cuda_runtime.h>
#include <cuda_bf16.h>
#include <cstdint>

#define HC 4
#define CDIM 256
#define KDIM 1024
#define MDIM 24
#define TMAX_IT 20
#define RMS_EPS 1e-6f
#define SINK_EPS 1e-6f
#define POST_MULT 2.0f
#define TOK 128
#define THREADS 512

// ---- smem byte offsets ----
#define OFF_CS 256                     // 128 tok x 20 floats
#define OFF_AH 16384                   // A hi bf16 [128 x 264] = 67584
#define OFF_AL 83968                   // A lo
#define OFF_B  151552                  // 64 KB: two 32 KB half-buffers (phase D); lgp aliases
#define OFF_D  16384                   // f fp32 [128][264] = 135168 (aliases A tiles)
#define D_STR  264
#define A_STR  528
// phase-A aliases:
#define XA(b)  (OFF_AH + (b)*18432)    // x-chunk hi bf16 [128 x 72] stride 144 B
#define XL(b)  (OFF_AL + (b)*18432)
#define X_STR  144
#define OFF_LG OFF_B                   // float lgp[2][128][28] = 28672
#define SMEM_TOTAL 217088

typedef unsigned long long u64;

// W packed fragment-major: [kchunk 0..3][hi(32KB)|lo(32KB)]
__device__ __align__(16) char g_wpk[4 * 65536];
// phi packed: one uint4 per (gk 0..63, ns 0..2, lane): [bh 8B | bl 8B]
__device__ __align__(16) uint4 g_ppk[64 * 3 * 32];

// ---- helpers ----
__device__ __forceinline__ uint32_t smem_u32(const void* p) {
    uint32_t a;
    asm("{ .reg .u64 t; cvta.to.shared.u64 t, %1; cvt.u32.u64 %0, t; }" : "=r"(a) : "l"(p));
    return a;
}
#define CPA(dst, src) \
    asm volatile("cp.async.cg.shared.global [%0], [%1], 16;" :: "r"(dst), "l"(src) : "memory")
#define CPA_COMMIT() asm volatile("cp.async.commit_group;" ::: "memory")
#define CPA_WAIT1()  asm volatile("cp.async.wait_group 1;" ::: "memory")
#define CPA_WAIT0()  asm volatile("cp.async.wait_group 0;" ::: "memory")

__device__ __forceinline__ u64 pk2(float lo, float hi) {
    u64 r; asm("mov.b64 %0, {%1, %2};" : "=l"(r) : "f"(lo), "f"(hi)); return r;
}
__device__ __forceinline__ void upk2(u64 v, float& lo, float& hi) {
    asm("mov.b64 {%0, %1}, %2;" : "=f"(lo), "=f"(hi) : "l"(v));
}
__device__ __forceinline__ u64 fma2(u64 a, u64 b, u64 c) {
    u64 d; asm("fma.rn.f32x2 %0, %1, %2, %3;" : "=l"(d) : "l"(a), "l"(b), "l"(c)); return d;
}
__device__ __forceinline__ float sigmoidf_fast(float v) {
    return __fdividef(1.0f, 1.0f + __expf(-v));
}
__device__ __forceinline__ void split4(float4 v, uint2& h, uint2& l) {
    __nv_bfloat16 ax = __float2bfloat16(v.x), ay = __float2bfloat16(v.y),
                  az = __float2bfloat16(v.z), aw = __float2bfloat16(v.w);
    __nv_bfloat16 bx = __float2bfloat16(v.x - __bfloat162float(ax)),
                  by = __float2bfloat16(v.y - __bfloat162float(ay)),
                  bz = __float2bfloat16(v.z - __bfloat162float(az)),
                  bw = __float2bfloat16(v.w - __bfloat162float(aw));
    h.x = ((uint32_t)__bfloat16_as_ushort(ay) << 16) | __bfloat16_as_ushort(ax);
    h.y = ((uint32_t)__bfloat16_as_ushort(aw) << 16) | __bfloat16_as_ushort(az);
    l.x = ((uint32_t)__bfloat16_as_ushort(by) << 16) | __bfloat16_as_ushort(bx);
    l.y = ((uint32_t)__bfloat16_as_ushort(bw) << 16) | __bfloat16_as_ushort(bz);
}
__device__ __forceinline__ void mma_bf16(float4& d, uint4 a, uint2 b) {
    asm volatile("mma.sync.aligned.m16n8k16.row.col.f32.bf16.bf16.f32 "
        "{%0,%1,%2,%3}, {%4,%5,%6,%7}, {%8,%9}, {%0,%1,%2,%3};"
        : "+f"(d.x), "+f"(d.y), "+f"(d.z), "+f"(d.w)
        : "r"(a.x), "r"(a.y), "r"(a.z), "r"(a.w), "r"(b.x), "r"(b.y));
}
__device__ __forceinline__ uint32_t cvt2(float v0, float v1) {
    uint32_t r; asm("cvt.rn.bf16x2.f32 %0, %1, %2;" : "=r"(r) : "f"(v1), "f"(v0)); return r;
}

// =====================================================================
// fused pack: blocks [0,256) pack W, [256,352) pack phi
__global__ void pack_all(const float* __restrict__ W, const float* __restrict__ phi) {
    if (blockIdx.x < 256) {
        int i = blockIdx.x * 256 + threadIdx.x;
        int n = i >> 8, k = i & 255;
        float v = W[n * 256 + k];
        __nv_bfloat16 h = __float2bfloat16(v);
        __nv_bfloat16 l = __float2bfloat16(v - __bfloat162float(h));
        int kc = k >> 6, ks = (k & 63) >> 4, k_in = k & 15, ns = n >> 3;
        int lane = ((n & 7) << 2) | ((k_in >> 1) & 3);
        int off = (((ks * 32 + ns) * 32 + lane) << 3) + ((k_in >> 3) << 2) + ((k_in & 1) << 1);
        *(__nv_bfloat16*)(g_wpk + kc * 65536 + off)         = h;
        *(__nv_bfloat16*)(g_wpk + kc * 65536 + 32768 + off) = l;
    } else {
        int i = (blockIdx.x - 256) * 256 + threadIdx.x;   // 24576
        int m = i >> 10, k = i & 1023;
        float v = phi[k * 24 + m];
        __nv_bfloat16 h = __float2bfloat16(v);
        __nv_bfloat16 l = __float2bfloat16(v - __bfloat162float(h));
        int gk = k >> 4, k_in = k & 15, ns = m >> 3;
        int lane = ((m & 7) << 2) | ((k_in >> 1) & 3);
        char* base = (char*)&g_ppk[(gk * 3 + ns) * 32 + lane];
        int sub = ((k_in >> 3) << 2) + ((k_in & 1) << 1);
        *(__nv_bfloat16*)(base + sub)     = h;
        *(__nv_bfloat16*)(base + 8 + sub) = l;
    }
}

// =====================================================================
__global__ __launch_bounds__(THREADS, 1)
void mhc_mma(const float* __restrict__ x, const float* __restrict__ bvec,
             const float* __restrict__ apre_p, const float* __restrict__ apost_p,
             const float* __restrict__ ares_p, float* __restrict__ out)
{
    extern __shared__ char smem[];
    float* s_cs = (float*)(smem + OFF_CS);
    const uint32_t sb = smem_u32(smem);
    const int tid = threadIdx.x, lane = tid & 31, wid = tid >> 5;
    const int tok0 = blockIdx.x * TOK;
    const int t0 = wid * 8;

    const float apre = *apre_p, apost = *apost_p, ares = *ares_p;

    // ---------- Phase A: logits = x . phi via mma.sync (bf16 trunc-split) ----------
    const int amt = wid & 7;       // m-tile
    const int akh = wid >> 3;      // k half
    float4 DL0 = make_float4(0,0,0,0), DL1 = DL0, DL2 = DL0;

    #define CONV_CHUNK(KC, BUF) do {                                              \
        int tok_ = tid >> 2, kq_ = (tid & 3) * 16;                                \
        const float4* src_ = (const float4*)(x + (size_t)(tok0 + tok_) * KDIM     \
                                             + (KC) * 64 + kq_);                  \
        char* dh_ = smem + XA(BUF) + tok_ * X_STR + kq_ * 2;                      \
        char* dl_ = smem + XL(BUF) + tok_ * X_STR + kq_ * 2;                      \
        _Pragma("unroll")                                                         \
        for (int j_ = 0; j_ < 4; j_++) {                                          \
            float4 v_ = src_[j_];                                                 \
            uint32_t ux_ = __float_as_uint(v_.x), uy_ = __float_as_uint(v_.y);    \
            uint32_t uz_ = __float_as_uint(v_.z), uw_ = __float_as_uint(v_.w);    \
            uint32_t h01_ = __byte_perm(ux_, uy_, 0x7632);                        \
            uint32_t h23_ = __byte_perm(uz_, uw_, 0x7632);                        \
            float l0_ = v_.x - __uint_as_float(ux_ & 0xFFFF0000u);                \
            float l1_ = v_.y - __uint_as_float(uy_ & 0xFFFF0000u);                \
            float l2_ = v_.z - __uint_as_float(uz_ & 0xFFFF0000u);                \
            float l3_ = v_.w - __uint_as_float(uw_ & 0xFFFF0000u);                \
            *(uint2*)(dh_ + j_ * 8) = make_uint2(h01_, h23_);                     \
            *(uint2*)(dl_ + j_ * 8) = make_uint2(cvt2(l0_, l1_), cvt2(l2_, l3_)); \
        }                                                                         \
    } while (0)

    // prefetch first phi B fragments
    uint4 Bc0, Bc1, Bc2;
    {
        int gk0 = akh * 2;
        Bc0 = g_ppk[gk0 * 96 + lane];
        Bc1 = g_ppk[gk0 * 96 + 32 + lane];
        Bc2 = g_ppk[gk0 * 96 + 64 + lane];
    }
    CONV_CHUNK(0, 0);
    __syncthreads();
    for (int kc = 0; kc < 16; kc++) {
        if (kc < 15) CONV_CHUNK(kc + 1, (kc + 1) & 1);
        const char* xah = smem + XA(kc & 1);
        const char* xal = smem + XL(kc & 1);
        const int r = amt * 16 + (lane >> 2);
        #pragma unroll
        for (int gl = 0; gl < 2; gl++) {
            int gkl = akh * 2 + gl;
            int gk  = kc * 4 + gkl;
            // prefetch next B fragments
            int gkn = (gl == 0) ? gk + 1 : ((kc < 15) ? gk + 3 : gk);
            uint4 Bn0 = g_ppk[gkn * 96 + lane];
            uint4 Bn1 = g_ppk[gkn * 96 + 32 + lane];
            uint4 Bn2 = g_ppk[gkn * 96 + 64 + lane];
            const char* pa = xah + r * X_STR + gkl * 32 + (lane & 3) * 4;
            const char* pl = xal + r * X_STR + gkl * 32 + (lane & 3) * 4;
            uint4 Ah, Al;
            Ah.x = *(const uint32_t*)pa;        Ah.y = *(const uint32_t*)(pa + 8 * X_STR);
            Ah.z = *(const uint32_t*)(pa + 16); Ah.w = *(const uint32_t*)(pa + 8 * X_STR + 16);
            Al.x = *(const uint32_t*)pl;        Al.y = *(const uint32_t*)(pl + 8 * X_STR);
            Al.z = *(const uint32_t*)(pl + 16); Al.w = *(const uint32_t*)(pl + 8 * X_STR + 16);
            mma_bf16(DL0, Ah, make_uint2(Bc0.x, Bc0.y));
            mma_bf16(DL0, Al, make_uint2(Bc0.x, Bc0.y));
            mma_bf16(DL0, Ah, make_uint2(Bc0.z, Bc0.w));
            mma_bf16(DL1, Ah, make_uint2(Bc1.x, Bc1.y));
            mma_bf16(DL1, Al, make_uint2(Bc1.x, Bc1.y));
            mma_bf16(DL1, Ah, make_uint2(Bc1.z, Bc1.w));
            mma_bf16(DL2, Ah, make_uint2(Bc2.x, Bc2.y));
            mma_bf16(DL2, Al, make_uint2(Bc2.x, Bc2.y));
            mma_bf16(DL2, Ah, make_uint2(Bc2.z, Bc2.w));
            Bc0 = Bn0; Bc1 = Bn1; Bc2 = Bn2;
        }
        __syncthreads();
    }

    // write k-half partials to lgp[2][128][28]
    float* lgp = (float*)(smem + OFF_LG);
    {
        int r = amt * 16 + (lane >> 2), cb = (lane & 3) * 2;
        #pragma unroll
        for (int ns = 0; ns < 3; ns++) {
            float4 Dv = (ns == 0) ? DL0 : (ns == 1) ? DL1 : DL2;
            int c = ns * 8 + cb;
            *(float2*)&lgp[(akh * 128 + r) * 28 + c]     = make_float2(Dv.x, Dv.y);
            *(float2*)&lgp[(akh * 128 + r + 8) * 28 + c] = make_float2(Dv.z, Dv.w);
        }
    }
    __syncthreads();

    float l8[8];
    #pragma unroll
    for (int t = 0; t < 8; t++)
        l8[t] = (lane < MDIM)
              ? lgp[(t0 + t) * 28 + lane] + lgp[(128 + t0 + t) * 28 + lane] : 0.0f;
    __syncthreads();   // all lgp reads done -> B region reusable

    // issue W halves 0,1 via cp.async (lands during Sinkhorn + phase C)
    #pragma unroll
    for (int h = 0; h < 2; h++) {
        const char* src = g_wpk + h * 32768;    // chunk 0 hi, lo
        uint32_t dst = sb + OFF_B + h * 32768;
        #pragma unroll
        for (int j = 0; j < 4; j++)
            CPA(dst + (j * THREADS + tid) * 16, src + (j * THREADS + tid) * 16);
        CPA_COMMIT();
    }

    const float bm = (lane < MDIM) ? bvec[lane] : 0.0f;
    float yv[8];
    #pragma unroll
    for (int t = 0; t < 8; t++) {
        float s = l8[t] * l8[t];
        s += __shfl_xor_sync(~0u, s, 16); s += __shfl_xor_sync(~0u, s, 8);
        s += __shfl_xor_sync(~0u, s, 4);  s += __shfl_xor_sync(~0u, s, 2);
        s += __shfl_xor_sync(~0u, s, 1);
        yv[t] = l8[t] * rsqrtf(s * (1.0f / 24.0f) + RMS_EPS) + bm;
    }

    // ---------- Phase B: Sinkhorn ----------
    float P[4];
    #pragma unroll
    for (int tp = 0; tp < 4; tp++) {
        int src = 8 + (lane & 15);
        float ra = __shfl_sync(~0u, yv[2*tp], src);
        float rb = __shfl_sync(~0u, yv[2*tp+1], src);
        P[tp] = __expf(ares * ((lane < 16) ? ra : rb));
    }
    #pragma unroll
    for (int it = 0; it < TMAX_IT; it++) {
        #pragma unroll
        for (int tp = 0; tp < 4; tp++) {
            float s1 = P[tp] + __shfl_xor_sync(~0u, P[tp], 1);
            s1 += __shfl_xor_sync(~0u, s1, 2);
            P[tp] = __fdividef(P[tp], s1 + SINK_EPS);
        }
        #pragma unroll
        for (int tp = 0; tp < 4; tp++) {
            float s1 = P[tp] + __shfl_xor_sync(~0u, P[tp], 4);
            s1 += __shfl_xor_sync(~0u, s1, 8);
            P[tp] = __fdividef(P[tp], s1 + SINK_EPS);
        }
    }
    #pragma unroll
    for (int tp = 0; tp < 4; tp++) {
        int tl = t0 + 2*tp;
        if (lane < 16) s_cs[tl * 20 + lane] = P[tp];
        else           s_cs[(tl + 1) * 20 + (lane - 16)] = P[tp];
    }

    // ---------- Phase C: h_post + xin -> A tiles (bf16 hi/lo, pad 264) ----------
    #pragma unroll
    for (int t = 0; t < 8; t++) {
        int tl = t0 + t, tok = tok0 + tl;
        float yp = __shfl_sync(~0u, yv[t], 4 + (lane & 3));
        if (lane < 4) s_cs[tl * 20 + 16 + lane] = POST_MULT * sigmoidf_fast(apost * yp);
        float hp0 = sigmoidf_fast(apre * __shfl_sync(~0u, yv[t], 0));
        float hp1 = sigmoidf_fast(apre * __shfl_sync(~0u, yv[t], 1));
        float hp2 = sigmoidf_fast(apre * __shfl_sync(~0u, yv[t], 2));
        float hp3 = sigmoidf_fast(apre * __shfl_sync(~0u, yv[t], 3));
        const float4* xt = (const float4*)(x + (size_t)tok * KDIM);
        float4 sA = make_float4(0,0,0,0), sB = make_float4(0,0,0,0);
        #pragma unroll
        for (int i = 0; i < HC; i++) {
            float hp = (i==0)?hp0:(i==1)?hp1:(i==2)?hp2:hp3;
            float4 a = xt[i * 64 + lane], b = xt[i * 64 + 32 + lane];
            sA.x = fmaf(hp,a.x,sA.x); sA.y = fmaf(hp,a.y,sA.y);
            sA.z = fmaf(hp,a.z,sA.z); sA.w = fmaf(hp,a.w,sA.w);
            sB.x = fmaf(hp,b.x,sB.x); sB.y = fmaf(hp,b.y,sB.y);
            sB.z = fmaf(hp,b.z,sB.z); sB.w = fmaf(hp,b.w,sB.w);
        }
        uint2 hA, lA, hB, lB;
        split4(sA, hA, lA); split4(sB, hB, lB);
        *(uint2*)(smem + OFF_AH + tl*A_STR + lane*8)       = hA;
        *(uint2*)(smem + OFF_AL + tl*A_STR + lane*8)       = lA;
        *(uint2*)(smem + OFF_AH + tl*A_STR + 256 + lane*8) = hB;
        *(uint2*)(smem + OFF_AL + tl*A_STR + 256 + lane*8) = lB;
    }
    __syncthreads();

    // ---------- Phase D: F = xin @ W^T, cp.async-pipelined hi/lo halves ----------
    const int mt = wid & 7;
    const int nh = wid >> 3;
    float4 D[16];
    #pragma unroll
    for (int j = 0; j < 16; j++) D[j] = make_float4(0,0,0,0);

    const char* pah = smem + OFF_AH + (mt*16 + (lane>>2))*A_STR + (lane&3)*4;
    const char* pal = smem + OFF_AL + (mt*16 + (lane>>2))*A_STR + (lane&3)*4;

    for (int ih = 0; ih < 8; ih++) {
        if (ih < 7) { CPA_WAIT1(); } else { CPA_WAIT0(); }
        __syncthreads();
        const int kc = ih >> 1, hl = ih & 1;
        const char* pb = smem + OFF_B + hl * 32768;
        if (hl == 0) {
            #pragma unroll
            for (int ks = 0; ks < 4; ks++) {
                int gko = (kc * 4 + ks) * 32;
                uint4 Ah, Al;
                Ah.x = *(const uint32_t*)(pah + gko);
                Ah.y = *(const uint32_t*)(pah + 8*A_STR + gko);
                Ah.z = *(const uint32_t*)(pah + gko + 16);
                Ah.w = *(const uint32_t*)(pah + 8*A_STR + gko + 16);
                Al.x = *(const uint32_t*)(pal + gko);
                Al.y = *(const uint32_t*)(pal + 8*A_STR + gko);
                Al.z = *(const uint32_t*)(pal + gko + 16);
                Al.w = *(const uint32_t*)(pal + 8*A_STR + gko + 16);
                const char* pbk = pb + ((ks*32 + nh*16)*32 + lane)*8;
                #pragma unroll
                for (int j = 0; j < 16; j++) {
                    uint2 bh = *(const uint2*)(pbk + j*256);
                    mma_bf16(D[j], Ah, bh);
                    mma_bf16(D[j], Al, bh);
                }
            }
        } else {
            #pragma unroll
            for (int ks = 0; ks < 4; ks++) {
                int gko = (kc * 4 + ks) * 32;
                uint4 Ah;
                Ah.x = *(const uint32_t*)(pah + gko);
                Ah.y = *(const uint32_t*)(pah + 8*A_STR + gko);
                Ah.z = *(const uint32_t*)(pah + gko + 16);
                Ah.w = *(const uint32_t*)(pah + 8*A_STR + gko + 16);
                const char* pbk = pb + ((ks*32 + nh*16)*32 + lane)*8;
                #pragma unroll
                for (int j = 0; j < 16; j++) {
                    uint2 bl = *(const uint2*)(pbk + j*256);
                    mma_bf16(D[j], Ah, bl);
                }
            }
        }
        __syncthreads();
        if (ih < 6) {
            int ihn = ih + 2;
            const char* src = g_wpk + (ihn >> 1) * 65536 + (ihn & 1) * 32768;
            uint32_t dst = sb + OFF_B + (ihn & 1) * 32768;
            #pragma unroll
            for (int j = 0; j < 4; j++)
                CPA(dst + (j * THREADS + tid) * 16, src + (j * THREADS + tid) * 16);
            CPA_COMMIT();
        }
    }

    // ---------- stage F into s_D fp32 [128][264] ----------
    float* sD = (float*)(smem + OFF_D);
    {
        int r0 = mt*16 + (lane>>2);
        int cb = nh*128 + (lane&3)*2;
        #pragma unroll
        for (int j = 0; j < 16; j++) {
            int col = cb + j*8;
            *(float2*)&sD[r0*D_STR + col]     = make_float2(D[j].x, D[j].y);
            *(float2*)&sD[(r0+8)*D_STR + col] = make_float2(D[j].z, D[j].w);
        }
    }
    __syncthreads();

    // ---------- epilogue: out = P@x + hpost * f ----------
    const int cx = lane;
    #pragma unroll
    for (int i = 0; i < 8; i++) {
        int tl = t0 + i, tok = tok0 + tl;
        const u64* xb = (const u64*)(x + (size_t)tok * KDIM);
        ulonglong2 xpA[HC], xpB[HC];
        #pragma unroll
        for (int ii = 0; ii < HC; ii++) {
            xpA[ii] = *(const ulonglong2*)(xb + ii * 128 + cx * 2);
            xpB[ii] = *(const ulonglong2*)(xb + ii * 128 + 64 + cx * 2);
        }
        float4 fA = *(const float4*)(sD + tl * D_STR + 4 * cx);
        float4 fB = *(const float4*)(sD + tl * D_STR + 128 + 4 * cx);
        u64* ob = (u64*)(out + (size_t)tok * KDIM);
        #pragma unroll
        for (int o = 0; o < HC; o++) {
            float hp = s_cs[tl * 20 + 16 + o];
            u64 hp2 = pk2(hp, hp);
            u64 r0 = fma2(hp2, pk2(fA.x, fA.y), 0ull);
            u64 r1 = fma2(hp2, pk2(fA.z, fA.w), 0ull);
            u64 r2 = fma2(hp2, pk2(fB.x, fB.y), 0ull);
            u64 r3 = fma2(hp2, pk2(fB.z, fB.w), 0ull);
            #pragma unroll
            for (int ii = 0; ii < HC; ii++) {
                float p = s_cs[tl * 20 + o * 4 + ii];
                u64 p2 = pk2(p, p);
                r0 = fma2(p2, xpA[ii].x, r0); r1 = fma2(p2, xpA[ii].y, r1);
                r2 = fma2(p2, xpB[ii].x, r2); r3 = fma2(p2, xpB[ii].y, r3);
            }
            *(ulonglong2*)(ob + o * 128 + cx * 2)      = make_ulonglong2(r0, r1);
            *(ulonglong2*)(ob + o * 128 + 64 + cx * 2) = make_ulonglong2(r2, r3);
        }
    }
}

// =====================================================================
extern "C" void kernel_launch(void* const* d_in, const int* in_sizes, int n_in,
                              void* d_out, int out_size)
{
    const float* x     = (const float*)d_in[0];
    const float* phi   = (const float*)d_in[1];
    const float* bvec  = (const float*)d_in[2];
    const float* apre  = (const float*)d_in[3];
    const float* apost = (const float*)d_in[4];
    const float* ares  = (const float*)d_in[5];
    const float* W     = (const float*)d_in[6];
    float* out = (float*)d_out;

    int tokens = in_sizes[0] / KDIM;

    static bool attr_set = false;
    if (!attr_set) {
        cudaFuncSetAttribute(mhc_mma, cudaFuncAttributeMaxDynamicSharedMemorySize, SMEM_TOTAL);
        attr_set = true;
    }
    pack_all<<<352, 256>>>(W, phi);
    mhc_mma<<<tokens / TOK, THREADS, SMEM_TOTAL>>>(x, bvec, apre, apost, ares, out);
}

// round 13
// speedup vs baseline: 2.9351x; 1.0171x over previous
#include <cuda_runtime.h>
#include <cuda_bf16.h>
#include <cstdint>

#define HC 4
#define CDIM 256
#define KDIM 1024
#define MDIM 24
#define TMAX_IT 20
#define RMS_EPS 1e-6f
#define SINK_EPS 1e-6f
#define POST_MULT 2.0f
#define TOK 128
#define THREADS 512

// ---- smem byte offsets ----
#define OFF_CS 256                     // 128 tok x 20 floats
#define OFF_AH 16384                   // A hi bf16 [128 x 264] = 67584
#define OFF_AL 83968                   // A lo
#define OFF_B  151552                  // 64 KB: two 32 KB half-buffers (phase D); lgp aliases
#define OFF_D  16384                   // f fp32 [128][264] = 135168 (aliases A tiles)
#define D_STR  264
#define A_STR  528
// phase-A aliases:
#define XA(b)  (OFF_AH + (b)*18432)    // x-chunk hi bf16 [128 x 72] stride 144 B
#define XL(b)  (OFF_AL + (b)*18432)
#define X_STR  144
#define OFF_LG OFF_B                   // float lgp[2][128][28] = 28672
#define SMEM_TOTAL 217088

typedef unsigned long long u64;

// W packed: 8 linear 32KB halves; half ih = kc*2 + kh (kh = ks>>1).
// record 16B per (s=ks&1, ns, lane): [bh 8B | bl 8B]
__device__ __align__(16) char g_wpk[8 * 32768];
// phi packed: one uint4 per (gk 0..63, ns 0..2, lane): [bh 8B | bl 8B]
__device__ __align__(16) uint4 g_ppk[64 * 3 * 32];

// ---- helpers ----
__device__ __forceinline__ uint32_t smem_u32(const void* p) {
    uint32_t a;
    asm("{ .reg .u64 t; cvta.to.shared.u64 t, %1; cvt.u32.u64 %0, t; }" : "=r"(a) : "l"(p));
    return a;
}
#define CPA(dst, src) \
    asm volatile("cp.async.cg.shared.global [%0], [%1], 16;" :: "r"(dst), "l"(src) : "memory")
#define CPA_COMMIT() asm volatile("cp.async.commit_group;" ::: "memory")
#define CPA_WAIT1()  asm volatile("cp.async.wait_group 1;" ::: "memory")
#define CPA_WAIT0()  asm volatile("cp.async.wait_group 0;" ::: "memory")

__device__ __forceinline__ void ldsm_x4(uint4& r, uint32_t addr) {
    asm volatile("ldmatrix.sync.aligned.m8n8.x4.shared.b16 {%0,%1,%2,%3}, [%4];"
        : "=r"(r.x), "=r"(r.y), "=r"(r.z), "=r"(r.w) : "r"(addr));
}
__device__ __forceinline__ u64 pk2(float lo, float hi) {
    u64 r; asm("mov.b64 %0, {%1, %2};" : "=l"(r) : "f"(lo), "f"(hi)); return r;
}
__device__ __forceinline__ void upk2(u64 v, float& lo, float& hi) {
    asm("mov.b64 {%0, %1}, %2;" : "=f"(lo), "=f"(hi) : "l"(v));
}
__device__ __forceinline__ u64 fma2(u64 a, u64 b, u64 c) {
    u64 d; asm("fma.rn.f32x2 %0, %1, %2, %3;" : "=l"(d) : "l"(a), "l"(b), "l"(c)); return d;
}
__device__ __forceinline__ float sigmoidf_fast(float v) {
    return __fdividef(1.0f, 1.0f + __expf(-v));
}
__device__ __forceinline__ void split4(float4 v, uint2& h, uint2& l) {
    __nv_bfloat16 ax = __float2bfloat16(v.x), ay = __float2bfloat16(v.y),
                  az = __float2bfloat16(v.z), aw = __float2bfloat16(v.w);
    __nv_bfloat16 bx = __float2bfloat16(v.x - __bfloat162float(ax)),
                  by = __float2bfloat16(v.y - __bfloat162float(ay)),
                  bz = __float2bfloat16(v.z - __bfloat162float(az)),
                  bw = __float2bfloat16(v.w - __bfloat162float(aw));
    h.x = ((uint32_t)__bfloat16_as_ushort(ay) << 16) | __bfloat16_as_ushort(ax);
    h.y = ((uint32_t)__bfloat16_as_ushort(aw) << 16) | __bfloat16_as_ushort(az);
    l.x = ((uint32_t)__bfloat16_as_ushort(by) << 16) | __bfloat16_as_ushort(bx);
    l.y = ((uint32_t)__bfloat16_as_ushort(bw) << 16) | __bfloat16_as_ushort(bz);
}
__device__ __forceinline__ void mma_bf16(float4& d, uint4 a, uint2 b) {
    asm volatile("mma.sync.aligned.m16n8k16.row.col.f32.bf16.bf16.f32 "
        "{%0,%1,%2,%3}, {%4,%5,%6,%7}, {%8,%9}, {%0,%1,%2,%3};"
        : "+f"(d.x), "+f"(d.y), "+f"(d.z), "+f"(d.w)
        : "r"(a.x), "r"(a.y), "r"(a.z), "r"(a.w), "r"(b.x), "r"(b.y));
}
__device__ __forceinline__ uint32_t cvt2(float v0, float v1) {
    uint32_t r; asm("cvt.rn.bf16x2.f32 %0, %1, %2;" : "=r"(r) : "f"(v1), "f"(v0)); return r;
}

// =====================================================================
// fused pack: blocks [0,256) pack W, [256,352) pack phi
__global__ void pack_all(const float* __restrict__ W, const float* __restrict__ phi) {
    if (blockIdx.x < 256) {
        int i = blockIdx.x * 256 + threadIdx.x;
        int n = i >> 8, k = i & 255;
        float v = W[n * 256 + k];
        __nv_bfloat16 h = __float2bfloat16(v);
        __nv_bfloat16 l = __float2bfloat16(v - __bfloat162float(h));
        int kc = k >> 6, ks = (k & 63) >> 4, k_in = k & 15, ns = n >> 3;
        int lane = ((n & 7) << 2) | ((k_in >> 1) & 3);
        int half = kc * 2 + (ks >> 1), s = ks & 1;
        char* base = g_wpk + half * 32768 + (((s * 32 + ns) * 32 + lane) << 4);
        int sub = ((k_in >> 3) << 2) + ((k_in & 1) << 1);
        *(__nv_bfloat16*)(base + sub)     = h;
        *(__nv_bfloat16*)(base + 8 + sub) = l;
    } else {
        int i = (blockIdx.x - 256) * 256 + threadIdx.x;   // 24576
        int m = i >> 10, k = i & 1023;
        float v = phi[k * 24 + m];
        __nv_bfloat16 h = __float2bfloat16(v);
        __nv_bfloat16 l = __float2bfloat16(v - __bfloat162float(h));
        int gk = k >> 4, k_in = k & 15, ns = m >> 3;
        int lane = ((m & 7) << 2) | ((k_in >> 1) & 3);
        char* base = (char*)&g_ppk[(gk * 3 + ns) * 32 + lane];
        int sub = ((k_in >> 3) << 2) + ((k_in & 1) << 1);
        *(__nv_bfloat16*)(base + sub)     = h;
        *(__nv_bfloat16*)(base + 8 + sub) = l;
    }
}

// =====================================================================
__global__ __launch_bounds__(THREADS, 1)
void mhc_mma(const float* __restrict__ x, const float* __restrict__ bvec,
             const float* __restrict__ apre_p, const float* __restrict__ apost_p,
             const float* __restrict__ ares_p, float* __restrict__ out)
{
    extern __shared__ char smem[];
    float* s_cs = (float*)(smem + OFF_CS);
    const uint32_t sb = smem_u32(smem);
    const int tid = threadIdx.x, lane = tid & 31, wid = tid >> 5;
    const int tok0 = blockIdx.x * TOK;
    const int t0 = wid * 8;

    const float apre = *apre_p, apost = *apost_p, ares = *ares_p;

    // ---------- Phase A: logits = x . phi via mma.sync (bf16 trunc-split) ----------
    const int amt = wid & 7;       // m-tile
    const int akh = wid >> 3;      // k half
    float4 DL0 = make_float4(0,0,0,0), DL1 = DL0, DL2 = DL0;

    #define CONV_CHUNK(KC, BUF) do {                                              \
        int tok_ = tid >> 2, kq_ = (tid & 3) * 16;                                \
        const float4* src_ = (const float4*)(x + (size_t)(tok0 + tok_) * KDIM     \
                                             + (KC) * 64 + kq_);                  \
        char* dh_ = smem + XA(BUF) + tok_ * X_STR + kq_ * 2;                      \
        char* dl_ = smem + XL(BUF) + tok_ * X_STR + kq_ * 2;                      \
        _Pragma("unroll")                                                         \
        for (int j_ = 0; j_ < 4; j_++) {                                          \
            float4 v_ = src_[j_];                                                 \
            uint32_t ux_ = __float_as_uint(v_.x), uy_ = __float_as_uint(v_.y);    \
            uint32_t uz_ = __float_as_uint(v_.z), uw_ = __float_as_uint(v_.w);    \
            uint32_t h01_ = __byte_perm(ux_, uy_, 0x7632);                        \
            uint32_t h23_ = __byte_perm(uz_, uw_, 0x7632);                        \
            float l0_ = v_.x - __uint_as_float(ux_ & 0xFFFF0000u);                \
            float l1_ = v_.y - __uint_as_float(uy_ & 0xFFFF0000u);                \
            float l2_ = v_.z - __uint_as_float(uz_ & 0xFFFF0000u);                \
            float l3_ = v_.w - __uint_as_float(uw_ & 0xFFFF0000u);                \
            *(uint2*)(dh_ + j_ * 8) = make_uint2(h01_, h23_);                     \
            *(uint2*)(dl_ + j_ * 8) = make_uint2(cvt2(l0_, l1_), cvt2(l2_, l3_)); \
        }                                                                         \
    } while (0)

    // prefetch first phi B fragments
    uint4 Bc0, Bc1, Bc2;
    {
        int gk0 = akh * 2;
        Bc0 = g_ppk[gk0 * 96 + lane];
        Bc1 = g_ppk[gk0 * 96 + 32 + lane];
        Bc2 = g_ppk[gk0 * 96 + 64 + lane];
    }
    CONV_CHUNK(0, 0);
    __syncthreads();
    // ldmatrix lane base for phase A (row = lane&15, k-block = lane>>4)
    const uint32_t arow_off = (uint32_t)(amt * 16 + (lane & 15)) * X_STR + (lane >> 4) * 16;
    for (int kc = 0; kc < 16; kc++) {
        if (kc < 15) CONV_CHUNK(kc + 1, (kc + 1) & 1);
        const uint32_t xah_u = sb + XA(kc & 1) + arow_off;
        const uint32_t xal_u = sb + XL(kc & 1) + arow_off;
        #pragma unroll
        for (int gl = 0; gl < 2; gl++) {
            int gkl = akh * 2 + gl;
            int gk  = kc * 4 + gkl;
            int gkn = (gl == 0) ? gk + 1 : ((kc < 15) ? gk + 3 : gk);
            uint4 Bn0 = g_ppk[gkn * 96 + lane];
            uint4 Bn1 = g_ppk[gkn * 96 + 32 + lane];
            uint4 Bn2 = g_ppk[gkn * 96 + 64 + lane];
            uint4 Ah, Al;
            ldsm_x4(Ah, xah_u + gkl * 32);
            ldsm_x4(Al, xal_u + gkl * 32);
            mma_bf16(DL0, Ah, make_uint2(Bc0.x, Bc0.y));
            mma_bf16(DL0, Al, make_uint2(Bc0.x, Bc0.y));
            mma_bf16(DL0, Ah, make_uint2(Bc0.z, Bc0.w));
            mma_bf16(DL1, Ah, make_uint2(Bc1.x, Bc1.y));
            mma_bf16(DL1, Al, make_uint2(Bc1.x, Bc1.y));
            mma_bf16(DL1, Ah, make_uint2(Bc1.z, Bc1.w));
            mma_bf16(DL2, Ah, make_uint2(Bc2.x, Bc2.y));
            mma_bf16(DL2, Al, make_uint2(Bc2.x, Bc2.y));
            mma_bf16(DL2, Ah, make_uint2(Bc2.z, Bc2.w));
            Bc0 = Bn0; Bc1 = Bn1; Bc2 = Bn2;
        }
        __syncthreads();
    }

    // write k-half partials to lgp[2][128][28]
    float* lgp = (float*)(smem + OFF_LG);
    {
        int r = amt * 16 + (lane >> 2), cb = (lane & 3) * 2;
        #pragma unroll
        for (int ns = 0; ns < 3; ns++) {
            float4 Dv = (ns == 0) ? DL0 : (ns == 1) ? DL1 : DL2;
            int c = ns * 8 + cb;
            *(float2*)&lgp[(akh * 128 + r) * 28 + c]     = make_float2(Dv.x, Dv.y);
            *(float2*)&lgp[(akh * 128 + r + 8) * 28 + c] = make_float2(Dv.z, Dv.w);
        }
    }
    __syncthreads();

    float l8[8];
    #pragma unroll
    for (int t = 0; t < 8; t++)
        l8[t] = (lane < MDIM)
              ? lgp[(t0 + t) * 28 + lane] + lgp[(128 + t0 + t) * 28 + lane] : 0.0f;
    __syncthreads();   // all lgp reads done -> B region reusable

    // issue W halves 0,1 via cp.async (lands during Sinkhorn + phase C)
    #pragma unroll
    for (int h = 0; h < 2; h++) {
        const char* src = g_wpk + h * 32768;
        uint32_t dst = sb + OFF_B + h * 32768;
        #pragma unroll
        for (int j = 0; j < 4; j++)
            CPA(dst + (j * THREADS + tid) * 16, src + (j * THREADS + tid) * 16);
        CPA_COMMIT();
    }

    const float bm = (lane < MDIM) ? bvec[lane] : 0.0f;
    float yv[8];
    #pragma unroll
    for (int t = 0; t < 8; t++) {
        float s = l8[t] * l8[t];
        s += __shfl_xor_sync(~0u, s, 16); s += __shfl_xor_sync(~0u, s, 8);
        s += __shfl_xor_sync(~0u, s, 4);  s += __shfl_xor_sync(~0u, s, 2);
        s += __shfl_xor_sync(~0u, s, 1);
        yv[t] = l8[t] * rsqrtf(s * (1.0f / 24.0f) + RMS_EPS) + bm;
    }

    // ---------- Phase B: Sinkhorn ----------
    float P[4];
    #pragma unroll
    for (int tp = 0; tp < 4; tp++) {
        int src = 8 + (lane & 15);
        float ra = __shfl_sync(~0u, yv[2*tp], src);
        float rb = __shfl_sync(~0u, yv[2*tp+1], src);
        P[tp] = __expf(ares * ((lane < 16) ? ra : rb));
    }
    #pragma unroll
    for (int it = 0; it < TMAX_IT; it++) {
        #pragma unroll
        for (int tp = 0; tp < 4; tp++) {
            float s1 = P[tp] + __shfl_xor_sync(~0u, P[tp], 1);
            s1 += __shfl_xor_sync(~0u, s1, 2);
            P[tp] = __fdividef(P[tp], s1 + SINK_EPS);
        }
        #pragma unroll
        for (int tp = 0; tp < 4; tp++) {
            float s1 = P[tp] + __shfl_xor_sync(~0u, P[tp], 4);
            s1 += __shfl_xor_sync(~0u, s1, 8);
            P[tp] = __fdividef(P[tp], s1 + SINK_EPS);
        }
    }
    #pragma unroll
    for (int tp = 0; tp < 4; tp++) {
        int tl = t0 + 2*tp;
        if (lane < 16) s_cs[tl * 20 + lane] = P[tp];
        else           s_cs[(tl + 1) * 20 + (lane - 16)] = P[tp];
    }

    // ---------- Phase C: h_post + xin -> A tiles (bf16 hi/lo, pad 264) ----------
    #pragma unroll
    for (int t = 0; t < 8; t++) {
        int tl = t0 + t, tok = tok0 + tl;
        float yp = __shfl_sync(~0u, yv[t], 4 + (lane & 3));
        if (lane < 4) s_cs[tl * 20 + 16 + lane] = POST_MULT * sigmoidf_fast(apost * yp);
        float hp0 = sigmoidf_fast(apre * __shfl_sync(~0u, yv[t], 0));
        float hp1 = sigmoidf_fast(apre * __shfl_sync(~0u, yv[t], 1));
        float hp2 = sigmoidf_fast(apre * __shfl_sync(~0u, yv[t], 2));
        float hp3 = sigmoidf_fast(apre * __shfl_sync(~0u, yv[t], 3));
        const float4* xt = (const float4*)(x + (size_t)tok * KDIM);
        float4 sA = make_float4(0,0,0,0), sB = make_float4(0,0,0,0);
        #pragma unroll
        for (int i = 0; i < HC; i++) {
            float hp = (i==0)?hp0:(i==1)?hp1:(i==2)?hp2:hp3;
            float4 a = xt[i * 64 + lane], b = xt[i * 64 + 32 + lane];
            sA.x = fmaf(hp,a.x,sA.x); sA.y = fmaf(hp,a.y,sA.y);
            sA.z = fmaf(hp,a.z,sA.z); sA.w = fmaf(hp,a.w,sA.w);
            sB.x = fmaf(hp,b.x,sB.x); sB.y = fmaf(hp,b.y,sB.y);
            sB.z = fmaf(hp,b.z,sB.z); sB.w = fmaf(hp,b.w,sB.w);
        }
        uint2 hA, lA, hB, lB;
        split4(sA, hA, lA); split4(sB, hB, lB);
        *(uint2*)(smem + OFF_AH + tl*A_STR + lane*8)       = hA;
        *(uint2*)(smem + OFF_AL + tl*A_STR + lane*8)       = lA;
        *(uint2*)(smem + OFF_AH + tl*A_STR + 256 + lane*8) = hB;
        *(uint2*)(smem + OFF_AL + tl*A_STR + 256 + lane*8) = lB;
    }
    __syncthreads();

    // ---------- Phase D: F = xin @ W^T, cp.async-pipelined, fused hi/lo records ----------
    const int mt = wid & 7;
    const int nh = wid >> 3;
    float4 D[16];
    #pragma unroll
    for (int j = 0; j < 16; j++) D[j] = make_float4(0,0,0,0);

    const uint32_t drow_off = (uint32_t)(mt * 16 + (lane & 15)) * A_STR + (lane >> 4) * 16;
    const uint32_t pah_u = sb + OFF_AH + drow_off;
    const uint32_t pal_u = sb + OFF_AL + drow_off;

    for (int ih = 0; ih < 8; ih++) {
        if (ih < 7) { CPA_WAIT1(); } else { CPA_WAIT0(); }
        __syncthreads();
        const int kc = ih >> 1, kh = ih & 1;
        const char* pbase = smem + OFF_B + (ih & 1) * 32768;
        #pragma unroll
        for (int s = 0; s < 2; s++) {
            int ks = kh * 2 + s;
            int gko = (kc * 4 + ks) * 32;
            uint4 Ah, Al;
            ldsm_x4(Ah, pah_u + gko);
            ldsm_x4(Al, pal_u + gko);
            const char* pbk = pbase + ((s * 32 + nh * 16) * 32 + lane) * 16;
            #pragma unroll
            for (int j = 0; j < 16; j++) {
                uint4 B = *(const uint4*)(pbk + j * 512);
                mma_bf16(D[j], Ah, make_uint2(B.x, B.y));
                mma_bf16(D[j], Al, make_uint2(B.x, B.y));
                mma_bf16(D[j], Ah, make_uint2(B.z, B.w));
            }
        }
        __syncthreads();
        if (ih < 6) {
            int ihn = ih + 2;
            const char* src = g_wpk + ihn * 32768;
            uint32_t dst = sb + OFF_B + (ihn & 1) * 32768;
            #pragma unroll
            for (int j = 0; j < 4; j++)
                CPA(dst + (j * THREADS + tid) * 16, src + (j * THREADS + tid) * 16);
            CPA_COMMIT();
        }
    }

    // ---------- stage F into s_D fp32 [128][264] ----------
    float* sD = (float*)(smem + OFF_D);
    {
        int r0 = mt*16 + (lane>>2);
        int cb = nh*128 + (lane&3)*2;
        #pragma unroll
        for (int j = 0; j < 16; j++) {
            int col = cb + j*8;
            *(float2*)&sD[r0*D_STR + col]     = make_float2(D[j].x, D[j].y);
            *(float2*)&sD[(r0+8)*D_STR + col] = make_float2(D[j].z, D[j].w);
        }
    }
    __syncthreads();

    // ---------- epilogue: out = P@x + hpost * f ----------
    const int cx = lane;
    #pragma unroll
    for (int i = 0; i < 8; i++) {
        int tl = t0 + i, tok = tok0 + tl;
        const u64* xb = (const u64*)(x + (size_t)tok * KDIM);
        ulonglong2 xpA[HC], xpB[HC];
        #pragma unroll
        for (int ii = 0; ii < HC; ii++) {
            xpA[ii] = *(const ulonglong2*)(xb + ii * 128 + cx * 2);
            xpB[ii] = *(const ulonglong2*)(xb + ii * 128 + 64 + cx * 2);
        }
        float4 fA = *(const float4*)(sD + tl * D_STR + 4 * cx);
        float4 fB = *(const float4*)(sD + tl * D_STR + 128 + 4 * cx);
        u64* ob = (u64*)(out + (size_t)tok * KDIM);
        #pragma unroll
        for (int o = 0; o < HC; o++) {
            float hp = s_cs[tl * 20 + 16 + o];
            u64 hp2 = pk2(hp, hp);
            u64 r0 = fma2(hp2, pk2(fA.x, fA.y), 0ull);
            u64 r1 = fma2(hp2, pk2(fA.z, fA.w), 0ull);
            u64 r2 = fma2(hp2, pk2(fB.x, fB.y), 0ull);
            u64 r3 = fma2(hp2, pk2(fB.z, fB.w), 0ull);
            #pragma unroll
            for (int ii = 0; ii < HC; ii++) {
                float p = s_cs[tl * 20 + o * 4 + ii];
                u64 p2 = pk2(p, p);
                r0 = fma2(p2, xpA[ii].x, r0); r1 = fma2(p2, xpA[ii].y, r1);
                r2 = fma2(p2, xpB[ii].x, r2); r3 = fma2(p2, xpB[ii].y, r3);
            }
            *(ulonglong2*)(ob + o * 128 + cx * 2)      = make_ulonglong2(r0, r1);
            *(ulonglong2*)(ob + o * 128 + 64 + cx * 2) = make_ulonglong2(r2, r3);
        }
    }
}

// =====================================================================
extern "C" void kernel_launch(void* const* d_in, const int* in_sizes, int n_in,
                              void* d_out, int out_size)
{
    const float* x     = (const float*)d_in[0];
    const float* phi   = (const float*)d_in[1];
    const float* bvec  = (const float*)d_in[2];
    const float* apre  = (const float*)d_in[3];
    const float* apost = (const float*)d_in[4];
    const float* ares  = (const float*)d_in[5];
    const float* W     = (const float*)d_in[6];
    float* out = (float*)d_out;

    int tokens = in_sizes[0] / KDIM;

    static bool attr_set = false;
    if (!attr_set) {
        cudaFuncSetAttribute(mhc_mma, cudaFuncAttributeMaxDynamicSharedMemorySize, SMEM_TOTAL);
        attr_set = true;
    }
    pack_all<<<352, 256>>>(W, phi);
    mhc_mma<<<tokens / TOK, THREADS, SMEM_TOTAL>>>(x, bvec, apre, apost, ares, out);
}